// round 2
// baseline (speedup 1.0000x reference)
#include <cuda_runtime.h>
#include <math.h>

// ---------------- problem constants ----------------
constexpr int NT   = 2048;   // sequence length
constexpr int GB   = 128;    // phase-B persistent blocks
constexpr int COLS = 8;      // 1024 / GB columns per block

// ---------------- device scratch ----------------
__device__ float g_part[6 * 8 * 1024];
__device__ float g_biasvec[1024];
__device__ float g_X[NT * 1024];
__device__ float g_H[NT * 1024];
__device__ float g_U[NT * 1024];
__device__ float g_demb[NT * 64];
__device__ float g_ybase[NT * 1024];
__device__ float g_xchg[2][1024];
__device__ unsigned int g_flag[GB];

__device__ __forceinline__ float geluf(float x) {
    return 0.5f * x * (1.0f + erff(x * 0.7071067811865476f));
}
__device__ __forceinline__ float softplusf(float x) {
    return (x > 0.f) ? x + log1pf(expf(-x)) : log1pf(expf(x));
}
__device__ __forceinline__ void st_release(unsigned* p, unsigned v) {
    asm volatile("st.release.gpu.u32 [%0], %1;" :: "l"(p), "r"(v) : "memory");
}
__device__ __forceinline__ unsigned ld_relaxed(const unsigned* p) {
    unsigned v;
    asm volatile("ld.relaxed.gpu.u32 %0, [%1];" : "=r"(v) : "l"(p) : "memory");
    return v;
}
__device__ __forceinline__ void fence_acq() {
    asm volatile("fence.acq_rel.gpu;" ::: "memory");
}

// ---------------- reset (per replay) ----------------
__global__ void k_reset() {
    int i = threadIdx.x;
    if (i < GB) g_flag[i] = 0u;
}

// ---------------- K0: partials for P5 (s<5) and molrow (s==5) ----------------
__global__ void k0_part(const float* __restrict__ mol_vec,
                        const float* __restrict__ solvent_vecs,
                        const float* __restrict__ sp_proj_w,
                        const float* __restrict__ bh_proj_w) {
    int s = blockIdx.y, chunk = blockIdx.x, tid = threadIdx.x;
    const float* vec = (s < 5) ? (solvent_vecs + s * 1024) : mol_vec;
    const float* W   = (s < 5) ? (sp_proj_w + (size_t)s * 1024 * 1024) : bh_proj_w;
    float acc[4] = {0.f, 0.f, 0.f, 0.f};
    int i0 = chunk * 128;
    for (int i = i0; i < i0 + 128; i++) {
        float v = __ldg(&vec[i]);
        const float* Wr = W + (size_t)i * 1024;
#pragma unroll
        for (int u = 0; u < 4; u++) acc[u] += v * Wr[tid + 256 * u];
    }
#pragma unroll
    for (int u = 0; u < 4; u++)
        g_part[(s * 8 + chunk) * 1024 + tid + 256 * u] = acc[u];
}

__global__ void k0b(const float* __restrict__ bh_proj_b) {
    int j = blockIdx.x * 256 + threadIdx.x;
    float a = bh_proj_b[j];
#pragma unroll
    for (int p = 0; p < 8; p++) a += g_part[(40 + p) * 1024 + j];
    g_biasvec[j] = a;
}

__global__ void k1_sp0(const float* __restrict__ ratios,
                       const float* __restrict__ spb) {
    __shared__ float sr[5];
    int t = blockIdx.x, tid = threadIdx.x;
    if (tid < 5) sr[tid] = ratios[t * 5 + tid];
    __syncthreads();
#pragma unroll
    for (int u = 0; u < 4; u++) {
        int j = tid + 256 * u;
        float acc = spb[j];
#pragma unroll
        for (int s = 0; s < 5; s++) {
            float ps = 0.f;
#pragma unroll
            for (int p = 0; p < 8; p++) ps += g_part[(s * 8 + p) * 1024 + j];
            acc += sr[s] * ps;
        }
        g_X[(size_t)t * 1024 + j] = geluf(acc);
    }
}

__global__ void k_demb(const float* __restrict__ desc,
                       const float* __restrict__ dw,
                       const float* __restrict__ db) {
    int t = blockIdx.x, j = threadIdx.x;
    float acc = db[j];
#pragma unroll
    for (int k = 0; k < 6; k++) acc += desc[t * 6 + k] * dw[k * 64 + j];
    g_demb[t * 64 + j] = geluf(acc);
}

// ---------------- generic tiled fp32 GEMM ----------------
__global__ void k_gemm(const float* __restrict__ A, int lda,
                       const float* __restrict__ W, int ldw,
                       const float* __restrict__ bias,
                       const float* __restrict__ res,
                       float* __restrict__ C, int N, int K, int act) {
    __shared__ float As[16][64];
    __shared__ float Ws[16][68];
    int tid = threadIdx.x;
    int bx = blockIdx.x, by = blockIdx.y;
    int tx = tid & 15, ty = tid >> 4;
    float acc[4][4] = {};
    int mBase = by * 64, nBase = bx * 64;
    for (int k0 = 0; k0 < K; k0 += 16) {
        int mA = tid >> 2;
        int kA = (tid & 3) * 4;
        float4 av = *reinterpret_cast<const float4*>(&A[(size_t)(mBase + mA) * lda + k0 + kA]);
        As[kA + 0][mA] = av.x; As[kA + 1][mA] = av.y;
        As[kA + 2][mA] = av.z; As[kA + 3][mA] = av.w;
        int kW = tid >> 4;
        int nW = (tid & 15) * 4;
        float4 wv = *reinterpret_cast<const float4*>(&W[(size_t)(k0 + kW) * ldw + nBase + nW]);
        *reinterpret_cast<float4*>(&Ws[kW][nW]) = wv;
        __syncthreads();
#pragma unroll
        for (int kk = 0; kk < 16; kk++) {
            float4 a = *reinterpret_cast<const float4*>(&As[kk][ty * 4]);
            float4 b = *reinterpret_cast<const float4*>(&Ws[kk][tx * 4]);
            float aa[4] = {a.x, a.y, a.z, a.w};
            float bb[4] = {b.x, b.y, b.z, b.w};
#pragma unroll
            for (int i = 0; i < 4; i++)
#pragma unroll
                for (int j = 0; j < 4; j++) acc[i][j] += aa[i] * bb[j];
        }
        __syncthreads();
    }
#pragma unroll
    for (int i = 0; i < 4; i++) {
        int m = mBase + ty * 4 + i;
#pragma unroll
        for (int j = 0; j < 4; j++) {
            int n = nBase + tx * 4 + j;
            float v = acc[i][j];
            if (bias) v += bias[n];
            if (res)  v += res[(size_t)m * N + n];
            if (act)  v = geluf(v);
            C[(size_t)m * N + n] = v;
        }
    }
}

// ---------------- row LayerNorm (phase A) ----------------
__global__ void k_ln(const float* __restrict__ U, const float* __restrict__ g,
                     const float* __restrict__ b, float* __restrict__ X) {
    __shared__ float red[32];
    int t = blockIdx.x, tid = threadIdx.x;
    float v[4]; float s = 0.f, s2 = 0.f;
#pragma unroll
    for (int u = 0; u < 4; u++) {
        v[u] = U[(size_t)t * 1024 + tid + 256 * u];
        s += v[u]; s2 += v[u] * v[u];
    }
#pragma unroll
    for (int o = 16; o; o >>= 1) {
        s += __shfl_down_sync(~0u, s, o);
        s2 += __shfl_down_sync(~0u, s2, o);
    }
    int lane = tid & 31, w = tid >> 5;
    if (lane == 0) { red[w] = s; red[8 + w] = s2; }
    __syncthreads();
    if (tid == 0) {
        float ts = 0.f, ts2 = 0.f;
#pragma unroll
        for (int q = 0; q < 8; q++) { ts += red[q]; ts2 += red[8 + q]; }
        float m = ts * (1.f / 1024.f);
        float var = ts2 * (1.f / 1024.f) - m * m;
        red[16] = m; red[17] = rsqrtf(var + 1e-5f);
    }
    __syncthreads();
    float m = red[16], rs = red[17];
#pragma unroll
    for (int u = 0; u < 4; u++) {
        int i = tid + 256 * u;
        X[(size_t)t * 1024 + i] = g[i] * (v[u] - m) * rs + b[i];
    }
}

// ---------------- Phase B: persistent sequential kernel ----------------
// Per-block release-flag barrier + 2D (warp-per-k-slice) matvec.
// SMEM float offsets
constexpr int OFF_W    = 0;        // 6 * 8192
constexpr int OFF_LNG  = 49152;    // 3072
constexpr int OFF_LNB  = 52224;    // 3072
constexpr int OFF_R    = 55296;    // 1024
constexpr int OFF_X    = 56320;    // 1024
constexpr int OFF_RED  = 57344;    // 64
constexpr int OFF_B1   = 57408;    // 24
constexpr int OFF_B2   = 57432;    // 24
constexpr int OFF_SCAL = 57456;    // 8
constexpr int SMEMB_FLOATS = 57464;

__global__ void __launch_bounds__(256, 1) k_seq(
    const float* __restrict__ bh_fc1_w, const float* __restrict__ bh_fc1_b,
    const float* __restrict__ bh_fc2_w, const float* __restrict__ bh_fc2_b,
    const float* __restrict__ bh_ln_g,  const float* __restrict__ bh_ln_b,
    const float* __restrict__ bh_proj_w,
    const float* __restrict__ mu_w, const float* __restrict__ mu_b,
    const float* __restrict__ phi_w, const float* __restrict__ phi_b,
    const unsigned char* __restrict__ bmask,
    float* __restrict__ out) {
    extern __shared__ float sm[];
    float* sW    = sm + OFF_W;
    float* sLnG  = sm + OFF_LNG;
    float* sLnB  = sm + OFF_LNB;
    float* sR    = sm + OFF_R;
    float* sX    = sm + OFF_X;
    float* sRed  = sm + OFF_RED;
    float* sB1   = sm + OFF_B1;
    float* sB2   = sm + OFF_B2;
    float* sScal = sm + OFF_SCAL;

    int tid = threadIdx.x, lane = tid & 31, w = tid >> 5;
    int g = blockIdx.x;
    int cg = g * COLS;

    // one-time SMEM weight cache: column slices for both W1 and W2
    for (int m = 0; m < 6; m++) {
        const float* Wg = (m & 1) ? (bh_fc2_w + (size_t)(m >> 1) * 1048576)
                                  : (bh_fc1_w + (size_t)(m >> 1) * 1048576);
        for (int idx = tid; idx < 8192; idx += 256) {
            int c = idx & 7, row = idx >> 3;
            sW[m * 8192 + c * 1024 + row] = Wg[(size_t)row * 1024 + cg + c];
        }
    }
    for (int idx = tid; idx < 3072; idx += 256) {
        sLnG[idx] = bh_ln_g[idx];
        sLnB[idx] = bh_ln_b[idx];
    }
    for (int idx = tid; idx < 1024; idx += 256)
        sR[idx] = bh_proj_w[(size_t)2112 * 1024 + idx];
    if (tid < 24) {
        int i = tid / 8, c = tid % 8;
        sB1[tid] = bh_fc1_b[i * 1024 + cg + c];
        sB2[tid] = bh_fc2_b[i * 1024 + cg + c];
    }
    __syncthreads();

    float prev = -1.f;
    unsigned xn = 0;
    float mub = mu_b[0], phib = phi_b[0];
    const float4* mw4 = reinterpret_cast<const float4*>(mu_w);
    const float4* pw4 = reinterpret_cast<const float4*>(phi_w);

    for (int t = 0; t < NT; t++) {
        // z0 = gelu(ybase[t] + prev * r)
        {
            float4 y = *reinterpret_cast<const float4*>(&g_ybase[(size_t)t * 1024 + 4 * tid]);
            float4 r4 = *reinterpret_cast<float4*>(&sR[4 * tid]);
            float4 x0;
            x0.x = geluf(y.x + prev * r4.x);
            x0.y = geluf(y.y + prev * r4.y);
            x0.z = geluf(y.z + prev * r4.z);
            x0.w = geluf(y.w + prev * r4.w);
            *reinterpret_cast<float4*>(&sX[4 * tid]) = x0;
        }
        __syncthreads();

        for (int blk = 0; blk < 3; blk++) {
            // ---- h = gelu(x @ W1 + b1), 8 cols; warp w handles k-slice ----
            float acc[8];
            {
                float4 xa = *reinterpret_cast<float4*>(&sX[w * 128 + lane * 4]);
                const float* w1 = &sW[(blk * 2) * 8192 + w * 128 + lane * 4];
#pragma unroll
                for (int c = 0; c < 8; c++) {
                    float4 wv = *reinterpret_cast<const float4*>(&w1[c * 1024]);
                    acc[c] = xa.x * wv.x + xa.y * wv.y + xa.z * wv.z + xa.w * wv.w;
                }
            }
#pragma unroll
            for (int o = 16; o; o >>= 1)
#pragma unroll
                for (int c = 0; c < 8; c++) acc[c] += __shfl_xor_sync(~0u, acc[c], o);
            if (lane < 8) sRed[w * 8 + lane] = acc[lane];
            __syncthreads();
            unsigned bi = xn & 1;
            xn++;
            if (tid < 8) {
                float s = 0.f;
#pragma unroll
                for (int q = 0; q < 8; q++) s += sRed[q * 8 + tid];
                g_xchg[bi][cg + tid] = geluf(s + sB1[blk * 8 + tid]);
            }
            if (w == 0) {
                __syncwarp();
                if (lane == 0) st_release(&g_flag[g], xn);
                const unsigned* fp = g_flag + lane * 4;
                bool rdy;
                do {
                    unsigned a0 = ld_relaxed(fp);
                    unsigned a1 = ld_relaxed(fp + 1);
                    unsigned a2 = ld_relaxed(fp + 2);
                    unsigned a3 = ld_relaxed(fp + 3);
                    rdy = (a0 >= xn) & (a1 >= xn) & (a2 >= xn) & (a3 >= xn);
                } while (!__all_sync(~0u, rdy));
                fence_acq();
            }
            __syncthreads();

            // ---- u = h @ W2 + b2 + x; h slice read straight from L2 ----
            {
                float4 ha = *reinterpret_cast<const float4*>(&g_xchg[bi][w * 128 + lane * 4]);
                const float* w2 = &sW[(blk * 2 + 1) * 8192 + w * 128 + lane * 4];
#pragma unroll
                for (int c = 0; c < 8; c++) {
                    float4 wv = *reinterpret_cast<const float4*>(&w2[c * 1024]);
                    acc[c] = ha.x * wv.x + ha.y * wv.y + ha.z * wv.z + ha.w * wv.w;
                }
            }
#pragma unroll
            for (int o = 16; o; o >>= 1)
#pragma unroll
                for (int c = 0; c < 8; c++) acc[c] += __shfl_xor_sync(~0u, acc[c], o);
            if (lane < 8) sRed[w * 8 + lane] = acc[lane];
            __syncthreads();
            unsigned bi2 = xn & 1;
            xn++;
            if (tid < 8) {
                float s = 0.f;
#pragma unroll
                for (int q = 0; q < 8; q++) s += sRed[q * 8 + tid];
                g_xchg[bi2][cg + tid] = s + sB2[blk * 8 + tid] + sX[cg + tid];
            }
            if (w == 0) {
                __syncwarp();
                if (lane == 0) st_release(&g_flag[g], xn);
                const unsigned* fp = g_flag + lane * 4;
                bool rdy;
                do {
                    unsigned a0 = ld_relaxed(fp);
                    unsigned a1 = ld_relaxed(fp + 1);
                    unsigned a2 = ld_relaxed(fp + 2);
                    unsigned a3 = ld_relaxed(fp + 3);
                    rdy = (a0 >= xn) & (a1 >= xn) & (a2 >= xn) & (a3 >= xn);
                } while (!__all_sync(~0u, rdy));
                fence_acq();
            }
            __syncthreads();

            // ---- LayerNorm (redundant identical per block) ----
            float4 uv = *reinterpret_cast<const float4*>(&g_xchg[bi2][4 * tid]);
            float s1 = uv.x + uv.y + uv.z + uv.w;
            float s2 = uv.x * uv.x + uv.y * uv.y + uv.z * uv.z + uv.w * uv.w;
#pragma unroll
            for (int o = 16; o; o >>= 1) {
                s1 += __shfl_down_sync(~0u, s1, o);
                s2 += __shfl_down_sync(~0u, s2, o);
            }
            if (lane == 0) { sRed[w] = s1; sRed[8 + w] = s2; }
            __syncthreads();
            if (tid == 0) {
                float ts = 0.f, ts2 = 0.f;
#pragma unroll
                for (int q = 0; q < 8; q++) { ts += sRed[q]; ts2 += sRed[8 + q]; }
                float mm = ts * (1.f / 1024.f);
                float var = ts2 * (1.f / 1024.f) - mm * mm;
                sScal[0] = mm;
                sScal[1] = rsqrtf(var + 1e-5f);
            }
            __syncthreads();
            {
                float mm = sScal[0], rs = sScal[1];
                float4 lg = *reinterpret_cast<float4*>(&sLnG[blk * 1024 + 4 * tid]);
                float4 lb = *reinterpret_cast<float4*>(&sLnB[blk * 1024 + 4 * tid]);
                float4 xo;
                xo.x = lg.x * (uv.x - mm) * rs + lb.x;
                xo.y = lg.y * (uv.y - mm) * rs + lb.y;
                xo.z = lg.z * (uv.z - mm) * rs + lb.z;
                xo.w = lg.w * (uv.w - mm) * rs + lb.w;
                *reinterpret_cast<float4*>(&sX[4 * tid]) = xo;
            }
            __syncthreads();
        }

        // ---- mu / phi / rf (redundant identical per block) ----
        {
            float4 z = *reinterpret_cast<float4*>(&sX[4 * tid]);
            float4 mw = __ldg(&mw4[tid]);
            float4 pw = __ldg(&pw4[tid]);
            float pm = z.x * mw.x + z.y * mw.y + z.z * mw.z + z.w * mw.w;
            float pp = z.x * pw.x + z.y * pw.y + z.z * pw.z + z.w * pw.w;
#pragma unroll
            for (int o = 16; o; o >>= 1) {
                pm += __shfl_down_sync(~0u, pm, o);
                pp += __shfl_down_sync(~0u, pp, o);
            }
            if (lane == 0) { sRed[w] = pm; sRed[8 + w] = pp; }
            __syncthreads();
            if (tid == 0) {
                float tm = 0.f, tp = 0.f;
#pragma unroll
                for (int q = 0; q < 8; q++) { tm += sRed[q]; tp += sRed[8 + q]; }
                float mu = 1.f / (1.f + expf(-(tm + mub)));
                float phi = softplusf(tp + phib) + 2.f;
                bool isb = (bmask[t] != 0);
                float rf = (isb || prev < 0.f) ? mu : prev + mu * (1.f - prev);
                sScal[2] = rf;
                if (g == 0) {
                    out[t] = rf;
                    out[NT + t] = mu;
                    out[2 * NT + t] = phi;
                }
            }
            __syncthreads();
            prev = sScal[2];
        }
    }
}

// ---------------- launch ----------------
extern "C" void kernel_launch(void* const* d_in, const int* in_sizes, int n_in,
                              void* d_out, int out_size) {
    const float* mol_vec      = (const float*)d_in[0];
    const float* solvent_seq  = (const float*)d_in[1];
    const float* desc_seq     = (const float*)d_in[2];
    const float* solvent_vecs = (const float*)d_in[3];
    const unsigned char* bmask = (const unsigned char*)d_in[4];
    const float* sp_proj_w = (const float*)d_in[5];
    const float* sp_proj_b = (const float*)d_in[6];
    const float* sp_fc1_w  = (const float*)d_in[7];
    const float* sp_fc1_b  = (const float*)d_in[8];
    const float* sp_fc2_w  = (const float*)d_in[9];
    const float* sp_fc2_b  = (const float*)d_in[10];
    const float* sp_ln_g   = (const float*)d_in[11];
    const float* sp_ln_b   = (const float*)d_in[12];
    const float* desc_w    = (const float*)d_in[13];
    const float* desc_b    = (const float*)d_in[14];
    const float* bh_proj_w = (const float*)d_in[15];
    const float* bh_proj_b = (const float*)d_in[16];
    const float* bh_fc1_w  = (const float*)d_in[17];
    const float* bh_fc1_b  = (const float*)d_in[18];
    const float* bh_fc2_w  = (const float*)d_in[19];
    const float* bh_fc2_b  = (const float*)d_in[20];
    const float* bh_ln_g   = (const float*)d_in[21];
    const float* bh_ln_b   = (const float*)d_in[22];
    const float* mu_w      = (const float*)d_in[23];
    const float* mu_b      = (const float*)d_in[24];
    const float* phi_w     = (const float*)d_in[25];
    const float* phi_b     = (const float*)d_in[26];
    float* out = (float*)d_out;

    float *pX, *pH, *pU, *pD, *pY, *pBias;
    cudaGetSymbolAddress((void**)&pX, g_X);
    cudaGetSymbolAddress((void**)&pH, g_H);
    cudaGetSymbolAddress((void**)&pU, g_U);
    cudaGetSymbolAddress((void**)&pD, g_demb);
    cudaGetSymbolAddress((void**)&pY, g_ybase);
    cudaGetSymbolAddress((void**)&pBias, g_biasvec);

    k_reset<<<1, 128>>>();
    k0_part<<<dim3(8, 6), 256>>>(mol_vec, solvent_vecs, sp_proj_w, bh_proj_w);
    k0b<<<4, 256>>>(bh_proj_b);
    k1_sp0<<<NT, 256>>>(solvent_seq, sp_proj_b);

    for (int i = 0; i < 3; i++) {
        k_gemm<<<dim3(16, 32), 256>>>(pX, 1024, sp_fc1_w + (size_t)i * 1048576, 1024,
                                      sp_fc1_b + i * 1024, nullptr, pH, 1024, 1024, 1);
        k_gemm<<<dim3(16, 32), 256>>>(pH, 1024, sp_fc2_w + (size_t)i * 1048576, 1024,
                                      sp_fc2_b + i * 1024, pX, pU, 1024, 1024, 0);
        k_ln<<<NT, 256>>>(pU, sp_ln_g + i * 1024, sp_ln_b + i * 1024, pX);
    }

    k_demb<<<NT, 64>>>(desc_seq, desc_w, desc_b);

    k_gemm<<<dim3(16, 32), 256>>>(pX, 1024, bh_proj_w + (size_t)1024 * 1024, 1024,
                                  pBias, nullptr, pH, 1024, 1024, 0);
    k_gemm<<<dim3(16, 32), 256>>>(pD, 64, bh_proj_w + (size_t)2048 * 1024, 1024,
                                  nullptr, pH, pY, 1024, 64, 0);

    cudaFuncSetAttribute(k_seq, cudaFuncAttributeMaxDynamicSharedMemorySize,
                         SMEMB_FLOATS * (int)sizeof(float));
    k_seq<<<GB, 256, SMEMB_FLOATS * sizeof(float)>>>(
        bh_fc1_w, bh_fc1_b, bh_fc2_w, bh_fc2_b, bh_ln_g, bh_ln_b, bh_proj_w,
        mu_w, mu_b, phi_w, phi_b, bmask, out);
}

// round 9
// speedup vs baseline: 4.0346x; 4.0346x over previous
#include <cuda_runtime.h>
#include <math.h>

// ---------------- problem constants ----------------
constexpr int NT   = 2048;   // sequence length
constexpr int GB   = 128;    // phase-B persistent blocks
constexpr int COLS = 8;      // 1024 / GB columns per block

// ---------------- device scratch ----------------
struct __align__(128) ExSlot { float d[8]; unsigned ep; unsigned pad[23]; };

__device__ float g_part[6 * 8 * 1024];
__device__ float g_biasvec[1024];
__device__ float g_X[NT * 1024];
__device__ float g_H[NT * 1024];
__device__ float g_U[NT * 1024];
__device__ float g_demb[NT * 64];
__device__ float g_ybase[NT * 1024];
__device__ ExSlot g_ex[2][GB];

__device__ __forceinline__ float geluf(float x) {
    return 0.5f * x * (1.0f + erff(x * 0.7071067811865476f));
}
__device__ __forceinline__ float softplusf(float x) {
    return (x > 0.f) ? x + log1pf(expf(-x)) : log1pf(expf(x));
}
__device__ __forceinline__ void st_relaxed_f(float* p, float v) {
    asm volatile("st.relaxed.gpu.f32 [%0], %1;" :: "l"(p), "f"(v) : "memory");
}
__device__ __forceinline__ void st_release_u(unsigned* p, unsigned v) {
    asm volatile("st.release.gpu.u32 [%0], %1;" :: "l"(p), "r"(v) : "memory");
}
__device__ __forceinline__ unsigned ld_acquire_u(const unsigned* p) {
    unsigned v;
    asm volatile("ld.acquire.gpu.u32 %0, [%1];" : "=r"(v) : "l"(p) : "memory");
    return v;
}
// Acquire-poll with bounded backoff: fast path (first 64 iters) is a pure
// spin; beyond that, nanosleep to relieve LTS pressure (round-2 failure mode).
__device__ __forceinline__ void poll_ep(const unsigned* ep, unsigned rnd) {
    int it = 0;
    while (ld_acquire_u(ep) < rnd) {
        if (++it > 64) __nanosleep(64);
    }
}

// ---------------- reset (per replay) ----------------
__global__ void k_reset() {
    int i = threadIdx.x;  // 256 threads
    g_ex[i >> 7][i & 127].ep = 0u;
}

// ---------------- K0: partials for P5 (s<5) and molrow (s==5) ----------------
__global__ void k0_part(const float* __restrict__ mol_vec,
                        const float* __restrict__ solvent_vecs,
                        const float* __restrict__ sp_proj_w,
                        const float* __restrict__ bh_proj_w) {
    int s = blockIdx.y, chunk = blockIdx.x, tid = threadIdx.x;
    const float* vec = (s < 5) ? (solvent_vecs + s * 1024) : mol_vec;
    const float* W   = (s < 5) ? (sp_proj_w + (size_t)s * 1024 * 1024) : bh_proj_w;
    float acc[4] = {0.f, 0.f, 0.f, 0.f};
    int i0 = chunk * 128;
    for (int i = i0; i < i0 + 128; i++) {
        float v = __ldg(&vec[i]);
        const float* Wr = W + (size_t)i * 1024;
#pragma unroll
        for (int u = 0; u < 4; u++) acc[u] += v * Wr[tid + 256 * u];
    }
#pragma unroll
    for (int u = 0; u < 4; u++)
        g_part[(s * 8 + chunk) * 1024 + tid + 256 * u] = acc[u];
}

__global__ void k0b(const float* __restrict__ bh_proj_b) {
    int j = blockIdx.x * 256 + threadIdx.x;
    float a = bh_proj_b[j];
#pragma unroll
    for (int p = 0; p < 8; p++) a += g_part[(40 + p) * 1024 + j];
    g_biasvec[j] = a;
}

__global__ void k1_sp0(const float* __restrict__ ratios,
                       const float* __restrict__ spb) {
    __shared__ float sr[5];
    int t = blockIdx.x, tid = threadIdx.x;
    if (tid < 5) sr[tid] = ratios[t * 5 + tid];
    __syncthreads();
#pragma unroll
    for (int u = 0; u < 4; u++) {
        int j = tid + 256 * u;
        float acc = spb[j];
#pragma unroll
        for (int s = 0; s < 5; s++) {
            float ps = 0.f;
#pragma unroll
            for (int p = 0; p < 8; p++) ps += g_part[(s * 8 + p) * 1024 + j];
            acc += sr[s] * ps;
        }
        g_X[(size_t)t * 1024 + j] = geluf(acc);
    }
}

__global__ void k_demb(const float* __restrict__ desc,
                       const float* __restrict__ dw,
                       const float* __restrict__ db) {
    int t = blockIdx.x, j = threadIdx.x;
    float acc = db[j];
#pragma unroll
    for (int k = 0; k < 6; k++) acc += desc[t * 6 + k] * dw[k * 64 + j];
    g_demb[t * 64 + j] = geluf(acc);
}

// ---------------- generic tiled fp32 GEMM ----------------
__global__ void k_gemm(const float* __restrict__ A, int lda,
                       const float* __restrict__ W, int ldw,
                       const float* __restrict__ bias,
                       const float* __restrict__ res,
                       float* __restrict__ C, int N, int K, int act) {
    __shared__ float As[16][64];
    __shared__ float Ws[16][68];
    int tid = threadIdx.x;
    int bx = blockIdx.x, by = blockIdx.y;
    int tx = tid & 15, ty = tid >> 4;
    float acc[4][4] = {};
    int mBase = by * 64, nBase = bx * 64;
    for (int k0 = 0; k0 < K; k0 += 16) {
        int mA = tid >> 2;
        int kA = (tid & 3) * 4;
        float4 av = *reinterpret_cast<const float4*>(&A[(size_t)(mBase + mA) * lda + k0 + kA]);
        As[kA + 0][mA] = av.x; As[kA + 1][mA] = av.y;
        As[kA + 2][mA] = av.z; As[kA + 3][mA] = av.w;
        int kW = tid >> 4;
        int nW = (tid & 15) * 4;
        float4 wv = *reinterpret_cast<const float4*>(&W[(size_t)(k0 + kW) * ldw + nBase + nW]);
        *reinterpret_cast<float4*>(&Ws[kW][nW]) = wv;
        __syncthreads();
#pragma unroll
        for (int kk = 0; kk < 16; kk++) {
            float4 a = *reinterpret_cast<const float4*>(&As[kk][ty * 4]);
            float4 b = *reinterpret_cast<const float4*>(&Ws[kk][tx * 4]);
            float aa[4] = {a.x, a.y, a.z, a.w};
            float bb[4] = {b.x, b.y, b.z, b.w};
#pragma unroll
            for (int i = 0; i < 4; i++)
#pragma unroll
                for (int j = 0; j < 4; j++) acc[i][j] += aa[i] * bb[j];
        }
        __syncthreads();
    }
#pragma unroll
    for (int i = 0; i < 4; i++) {
        int m = mBase + ty * 4 + i;
#pragma unroll
        for (int j = 0; j < 4; j++) {
            int n = nBase + tx * 4 + j;
            float v = acc[i][j];
            if (bias) v += bias[n];
            if (res)  v += res[(size_t)m * N + n];
            if (act)  v = geluf(v);
            C[(size_t)m * N + n] = v;
        }
    }
}

// ---------------- row LayerNorm (phase A) ----------------
__global__ void k_ln(const float* __restrict__ U, const float* __restrict__ g,
                     const float* __restrict__ b, float* __restrict__ X) {
    __shared__ float red[32];
    int t = blockIdx.x, tid = threadIdx.x;
    float v[4]; float s = 0.f, s2 = 0.f;
#pragma unroll
    for (int u = 0; u < 4; u++) {
        v[u] = U[(size_t)t * 1024 + tid + 256 * u];
        s += v[u]; s2 += v[u] * v[u];
    }
#pragma unroll
    for (int o = 16; o; o >>= 1) {
        s += __shfl_down_sync(~0u, s, o);
        s2 += __shfl_down_sync(~0u, s2, o);
    }
    int lane = tid & 31, w = tid >> 5;
    if (lane == 0) { red[w] = s; red[8 + w] = s2; }
    __syncthreads();
    if (tid == 0) {
        float ts = 0.f, ts2 = 0.f;
#pragma unroll
        for (int q = 0; q < 8; q++) { ts += red[q]; ts2 += red[8 + q]; }
        float m = ts * (1.f / 1024.f);
        float var = ts2 * (1.f / 1024.f) - m * m;
        red[16] = m; red[17] = rsqrtf(var + 1e-5f);
    }
    __syncthreads();
    float m = red[16], rs = red[17];
#pragma unroll
    for (int u = 0; u < 4; u++) {
        int i = tid + 256 * u;
        X[(size_t)t * 1024 + i] = g[i] * (v[u] - m) * rs + b[i];
    }
}

// ---------------- Phase B: persistent sequential kernel ----------------
// SMEM float offsets
constexpr int OFF_W    = 0;        // 6 * 8192 (col-major slices)
constexpr int OFF_LNG  = 49152;    // 2 * 1024 (blocks 0,1 only)
constexpr int OFF_LNB  = 51200;    // 2 * 1024
constexpr int OFF_MG   = 53248;    // 1024 (mu_w * lnG2)
constexpr int OFF_PG   = 54272;    // 1024 (phi_w * lnG2)
constexpr int OFF_R    = 55296;    // 1024 (bh_proj_w row 2112)
constexpr int OFF_X    = 56320;    // 1024 working vector
constexpr int OFF_RED  = 57344;    // 64
constexpr int OFF_B1   = 57408;    // 24
constexpr int OFF_B2   = 57432;    // 24
constexpr int OFF_SCAL = 57456;    // 16
constexpr int SMEMB_FLOATS = 57472;

__global__ void __launch_bounds__(256, 1) k_seq(
    const float* __restrict__ bh_fc1_w, const float* __restrict__ bh_fc1_b,
    const float* __restrict__ bh_fc2_w, const float* __restrict__ bh_fc2_b,
    const float* __restrict__ bh_ln_g,  const float* __restrict__ bh_ln_b,
    const float* __restrict__ bh_proj_w,
    const float* __restrict__ mu_w, const float* __restrict__ mu_b,
    const float* __restrict__ phi_w, const float* __restrict__ phi_b,
    const unsigned char* __restrict__ bmask,
    float* __restrict__ out) {
    extern __shared__ float sm[];
    float* sW    = sm + OFF_W;
    float* sLnG  = sm + OFF_LNG;
    float* sLnB  = sm + OFF_LNB;
    float* sMG   = sm + OFF_MG;
    float* sPG   = sm + OFF_PG;
    float* sR    = sm + OFF_R;
    float* sX    = sm + OFF_X;
    float* sRed  = sm + OFF_RED;
    float* sB1   = sm + OFF_B1;
    float* sB2   = sm + OFF_B2;
    float* sScal = sm + OFF_SCAL;

    int tid = threadIdx.x, lane = tid & 31, w = tid >> 5;
    int g = blockIdx.x;
    int cg = g * COLS;

    // ---- one-time SMEM weight cache: column-major slices ----
    for (int m = 0; m < 6; m++) {
        const float* Wg = (m & 1) ? (bh_fc2_w + (size_t)(m >> 1) * 1048576)
                                  : (bh_fc1_w + (size_t)(m >> 1) * 1048576);
        for (int idx = tid; idx < 8192; idx += 256) {
            int c = idx & 7, row = idx >> 3;
            sW[m * 8192 + c * 1024 + row] = Wg[(size_t)row * 1024 + cg + c];
        }
    }
    for (int idx = tid; idx < 2048; idx += 256) {
        sLnG[idx] = bh_ln_g[idx];
        sLnB[idx] = bh_ln_b[idx];
    }
    for (int idx = tid; idx < 1024; idx += 256) {
        sR[idx]  = bh_proj_w[(size_t)2112 * 1024 + idx];
        sMG[idx] = mu_w[idx]  * bh_ln_g[2048 + idx];
        sPG[idx] = phi_w[idx] * bh_ln_g[2048 + idx];
    }
    if (tid < 24) {
        int i = tid / 8, c = tid % 8;
        sB1[tid] = bh_fc1_b[i * 1024 + cg + c];
        sB2[tid] = bh_fc2_b[i * 1024 + cg + c];
    }
    __syncthreads();

    // ---- precompute head constants: Smg=Σ mu_w*g2, Cmu=Σ mu_w*b2ln + mu_b; same for phi ----
    {
        float smg = 0.f, cmu = 0.f, spg = 0.f, cph = 0.f;
#pragma unroll
        for (int u = 0; u < 4; u++) {
            int i = tid + 256 * u;
            float lb2 = bh_ln_b[2048 + i];
            smg += sMG[i];
            cmu += mu_w[i] * lb2;
            spg += sPG[i];
            cph += phi_w[i] * lb2;
        }
#pragma unroll
        for (int o = 16; o; o >>= 1) {
            smg += __shfl_down_sync(~0u, smg, o);
            cmu += __shfl_down_sync(~0u, cmu, o);
            spg += __shfl_down_sync(~0u, spg, o);
            cph += __shfl_down_sync(~0u, cph, o);
        }
        if (lane == 0) {
            sRed[w] = smg; sRed[8 + w] = cmu; sRed[16 + w] = spg; sRed[24 + w] = cph;
        }
        __syncthreads();
        if (tid == 0) {
            float a = 0, b = 0, c = 0, d = 0;
#pragma unroll
            for (int q = 0; q < 8; q++) {
                a += sRed[q]; b += sRed[8 + q]; c += sRed[16 + q]; d += sRed[24 + q];
            }
            sScal[4] = a;                 // Smg
            sScal[5] = b + mu_b[0];       // Cmu
            sScal[6] = c;                 // Spg
            sScal[7] = d + phi_b[0];      // Cphi
        }
        __syncthreads();
    }
    float Smg = sScal[4], Cmu = sScal[5], Spg = sScal[6], Cph = sScal[7];

    float prev = -1.f;
    unsigned rnd = 0;

    for (int t = 0; t < NT; t++) {
        // ---- z0 = gelu(ybase[t] + prev * r) ----
        {
            float4 y  = *reinterpret_cast<const float4*>(&g_ybase[(size_t)t * 1024 + 4 * tid]);
            float4 r4 = *reinterpret_cast<float4*>(&sR[4 * tid]);
            float4 x0;
            x0.x = geluf(y.x + prev * r4.x);
            x0.y = geluf(y.y + prev * r4.y);
            x0.z = geluf(y.z + prev * r4.z);
            x0.w = geluf(y.w + prev * r4.w);
            *reinterpret_cast<float4*>(&sX[4 * tid]) = x0;
        }
        __syncthreads();

        for (int blk = 0; blk < 3; blk++) {
            // ======== seg A: h[cg+w] = gelu(x @ W1col + b1); warp-per-column ========
            {
                const float4* w1 = reinterpret_cast<const float4*>(&sW[(blk * 2) * 8192 + w * 1024]);
                const float4* x4 = reinterpret_cast<const float4*>(sX);
                float acc = 0.f;
#pragma unroll
                for (int i = 0; i < 8; i++) {
                    float4 xv = x4[i * 32 + lane];
                    float4 wv = w1[i * 32 + lane];
                    acc += xv.x * wv.x + xv.y * wv.y + xv.z * wv.z + xv.w * wv.w;
                }
#pragma unroll
                for (int o = 16; o; o >>= 1) acc += __shfl_xor_sync(~0u, acc, o);
                rnd++;
                if (lane == 0)
                    st_relaxed_f(&g_ex[rnd & 1][g].d[w], geluf(acc + sB1[blk * 8 + w]));
            }
            __syncthreads();
            if (tid == 0) st_release_u(&g_ex[rnd & 1][g].ep, rnd);

            // ======== seg B: consume h into sX (keep residual scalar first) ========
            float xres = sX[cg + w];
            if (lane < 16) {
                poll_ep(&g_ex[rnd & 1][w * 16 + lane].ep, rnd);
            }
            __syncthreads();
            {
                float4 hv = __ldcg(reinterpret_cast<const float4*>(
                    &g_ex[rnd & 1][tid >> 1].d[(tid & 1) * 4]));
                *reinterpret_cast<float4*>(&sX[4 * tid]) = hv;
            }
            __syncthreads();

            // ======== seg C: u[cg+w] = h @ W2col + b2 + xres ========
            {
                const float4* w2 = reinterpret_cast<const float4*>(&sW[(blk * 2 + 1) * 8192 + w * 1024]);
                const float4* h4 = reinterpret_cast<const float4*>(sX);
                float acc = 0.f;
#pragma unroll
                for (int i = 0; i < 8; i++) {
                    float4 hv = h4[i * 32 + lane];
                    float4 wv = w2[i * 32 + lane];
                    acc += hv.x * wv.x + hv.y * wv.y + hv.z * wv.z + hv.w * wv.w;
                }
#pragma unroll
                for (int o = 16; o; o >>= 1) acc += __shfl_xor_sync(~0u, acc, o);
                rnd++;
                if (lane == 0)
                    st_relaxed_f(&g_ex[rnd & 1][g].d[w], acc + sB2[blk * 8 + w] + xres);
            }
            __syncthreads();
            if (tid == 0) st_release_u(&g_ex[rnd & 1][g].ep, rnd);

            // ======== seg D: consume u; LayerNorm (+ fused head on blk 2) ========
            if (lane < 16) {
                poll_ep(&g_ex[rnd & 1][w * 16 + lane].ep, rnd);
            }
            __syncthreads();
            float4 uv = __ldcg(reinterpret_cast<const float4*>(
                &g_ex[rnd & 1][tid >> 1].d[(tid & 1) * 4]));

            if (blk < 2) {
                float s1 = uv.x + uv.y + uv.z + uv.w;
                float s2 = uv.x * uv.x + uv.y * uv.y + uv.z * uv.z + uv.w * uv.w;
#pragma unroll
                for (int o = 16; o; o >>= 1) {
                    s1 += __shfl_down_sync(~0u, s1, o);
                    s2 += __shfl_down_sync(~0u, s2, o);
                }
                if (lane == 0) { sRed[w] = s1; sRed[8 + w] = s2; }
                __syncthreads();
                if (tid == 0) {
                    float ts = 0.f, ts2 = 0.f;
#pragma unroll
                    for (int q = 0; q < 8; q++) { ts += sRed[q]; ts2 += sRed[8 + q]; }
                    float mm = ts * (1.f / 1024.f);
                    float var = ts2 * (1.f / 1024.f) - mm * mm;
                    sScal[0] = mm;
                    sScal[1] = rsqrtf(var + 1e-5f);
                }
                __syncthreads();
                float mm = sScal[0], rs = sScal[1];
                float4 lg = *reinterpret_cast<float4*>(&sLnG[blk * 1024 + 4 * tid]);
                float4 lb = *reinterpret_cast<float4*>(&sLnB[blk * 1024 + 4 * tid]);
                float4 xo;
                xo.x = lg.x * (uv.x - mm) * rs + lb.x;
                xo.y = lg.y * (uv.y - mm) * rs + lb.y;
                xo.z = lg.z * (uv.z - mm) * rs + lb.z;
                xo.w = lg.w * (uv.w - mm) * rs + lb.w;
                *reinterpret_cast<float4*>(&sX[4 * tid]) = xo;
                __syncthreads();
            } else {
                // fused LN + mu/phi head
                float4 mg = *reinterpret_cast<float4*>(&sMG[4 * tid]);
                float4 pg = *reinterpret_cast<float4*>(&sPG[4 * tid]);
                float s1 = uv.x + uv.y + uv.z + uv.w;
                float s2 = uv.x * uv.x + uv.y * uv.y + uv.z * uv.z + uv.w * uv.w;
                float pm = mg.x * uv.x + mg.y * uv.y + mg.z * uv.z + mg.w * uv.w;
                float pp = pg.x * uv.x + pg.y * uv.y + pg.z * uv.z + pg.w * uv.w;
#pragma unroll
                for (int o = 16; o; o >>= 1) {
                    s1 += __shfl_down_sync(~0u, s1, o);
                    s2 += __shfl_down_sync(~0u, s2, o);
                    pm += __shfl_down_sync(~0u, pm, o);
                    pp += __shfl_down_sync(~0u, pp, o);
                }
                if (lane == 0) {
                    sRed[w] = s1; sRed[8 + w] = s2; sRed[16 + w] = pm; sRed[24 + w] = pp;
                }
                __syncthreads();
                if (tid == 0) {
                    float ts = 0.f, ts2 = 0.f, tm = 0.f, tp = 0.f;
#pragma unroll
                    for (int q = 0; q < 8; q++) {
                        ts += sRed[q]; ts2 += sRed[8 + q];
                        tm += sRed[16 + q]; tp += sRed[24 + q];
                    }
                    float mm = ts * (1.f / 1024.f);
                    float var = ts2 * (1.f / 1024.f) - mm * mm;
                    float rs = rsqrtf(var + 1e-5f);
                    float zmu  = rs * (tm - mm * Smg) + Cmu;
                    float zphi = rs * (tp - mm * Spg) + Cph;
                    float mu  = 1.f / (1.f + expf(-zmu));
                    float phi = softplusf(zphi) + 2.f;
                    bool isb = (bmask[t] != 0);
                    float rf = (isb || prev < 0.f) ? mu : prev + mu * (1.f - prev);
                    sScal[2] = rf;
                    if (g == 0) {
                        out[t] = rf;
                        out[NT + t] = mu;
                        out[2 * NT + t] = phi;
                    }
                }
                __syncthreads();
                prev = sScal[2];
            }
        }
    }
}

// ---------------- launch ----------------
extern "C" void kernel_launch(void* const* d_in, const int* in_sizes, int n_in,
                              void* d_out, int out_size) {
    const float* mol_vec      = (const float*)d_in[0];
    const float* solvent_seq  = (const float*)d_in[1];
    const float* desc_seq     = (const float*)d_in[2];
    const float* solvent_vecs = (const float*)d_in[3];
    const unsigned char* bmask = (const unsigned char*)d_in[4];
    const float* sp_proj_w = (const float*)d_in[5];
    const float* sp_proj_b = (const float*)d_in[6];
    const float* sp_fc1_w  = (const float*)d_in[7];
    const float* sp_fc1_b  = (const float*)d_in[8];
    const float* sp_fc2_w  = (const float*)d_in[9];
    const float* sp_fc2_b  = (const float*)d_in[10];
    const float* sp_ln_g   = (const float*)d_in[11];
    const float* sp_ln_b   = (const float*)d_in[12];
    const float* desc_w    = (const float*)d_in[13];
    const float* desc_b    = (const float*)d_in[14];
    const float* bh_proj_w = (const float*)d_in[15];
    const float* bh_proj_b = (const float*)d_in[16];
    const float* bh_fc1_w  = (const float*)d_in[17];
    const float* bh_fc1_b  = (const float*)d_in[18];
    const float* bh_fc2_w  = (const float*)d_in[19];
    const float* bh_fc2_b  = (const float*)d_in[20];
    const float* bh_ln_g   = (const float*)d_in[21];
    const float* bh_ln_b   = (const float*)d_in[22];
    const float* mu_w      = (const float*)d_in[23];
    const float* mu_b      = (const float*)d_in[24];
    const float* phi_w     = (const float*)d_in[25];
    const float* phi_b     = (const float*)d_in[26];
    float* out = (float*)d_out;

    float *pX, *pH, *pU, *pD, *pY, *pBias;
    cudaGetSymbolAddress((void**)&pX, g_X);
    cudaGetSymbolAddress((void**)&pH, g_H);
    cudaGetSymbolAddress((void**)&pU, g_U);
    cudaGetSymbolAddress((void**)&pD, g_demb);
    cudaGetSymbolAddress((void**)&pY, g_ybase);
    cudaGetSymbolAddress((void**)&pBias, g_biasvec);

    k_reset<<<1, 256>>>();
    k0_part<<<dim3(8, 6), 256>>>(mol_vec, solvent_vecs, sp_proj_w, bh_proj_w);
    k0b<<<4, 256>>>(bh_proj_b);
    k1_sp0<<<NT, 256>>>(solvent_seq, sp_proj_b);

    for (int i = 0; i < 3; i++) {
        k_gemm<<<dim3(16, 32), 256>>>(pX, 1024, sp_fc1_w + (size_t)i * 1048576, 1024,
                                      sp_fc1_b + i * 1024, nullptr, pH, 1024, 1024, 1);
        k_gemm<<<dim3(16, 32), 256>>>(pH, 1024, sp_fc2_w + (size_t)i * 1048576, 1024,
                                      sp_fc2_b + i * 1024, pX, pU, 1024, 1024, 0);
        k_ln<<<NT, 256>>>(pU, sp_ln_g + i * 1024, sp_ln_b + i * 1024, pX);
    }

    k_demb<<<NT, 64>>>(desc_seq, desc_w, desc_b);

    k_gemm<<<dim3(16, 32), 256>>>(pX, 1024, bh_proj_w + (size_t)1024 * 1024, 1024,
                                  pBias, nullptr, pH, 1024, 1024, 0);
    k_gemm<<<dim3(16, 32), 256>>>(pD, 64, bh_proj_w + (size_t)2048 * 1024, 1024,
                                  nullptr, pH, pY, 1024, 64, 0);

    cudaFuncSetAttribute(k_seq, cudaFuncAttributeMaxDynamicSharedMemorySize,
                         SMEMB_FLOATS * (int)sizeof(float));
    k_seq<<<GB, 256, SMEMB_FLOATS * sizeof(float)>>>(
        bh_fc1_w, bh_fc1_b, bh_fc2_w, bh_fc2_b, bh_ln_g, bh_ln_b, bh_proj_w,
        mu_w, mu_b, phi_w, phi_b, bmask, out);
}

// round 14
// speedup vs baseline: 5.2657x; 1.3051x over previous
#include <cuda_runtime.h>
#include <math.h>

// ---------------- problem constants ----------------
constexpr int NT   = 2048;   // sequence length
constexpr int GB   = 128;    // phase-B persistent blocks
constexpr int COLS = 8;      // 1024 / GB columns per block

// ---------------- device scratch ----------------
struct __align__(128) Cnt { unsigned v; unsigned pad[31]; };

__device__ float g_part[6 * 8 * 1024];
__device__ float g_biasvec[1024];
__device__ float g_X[NT * 1024];
__device__ float g_H[NT * 1024];
__device__ float g_U[NT * 1024];
__device__ float g_demb[NT * 64];
__device__ float g_ybase[NT * 1024];
__device__ float g_xchg[2][1024];
__device__ Cnt g_cnt[8];

__device__ __forceinline__ float geluf(float x) {
    return 0.5f * x * (1.0f + erff(x * 0.7071067811865476f));
}
__device__ __forceinline__ float softplusf(float x) {
    return (x > 0.f) ? x + log1pf(expf(-x)) : log1pf(expf(x));
}
__device__ __forceinline__ void st_relaxed_f(float* p, float v) {
    asm volatile("st.relaxed.gpu.f32 [%0], %1;" :: "l"(p), "f"(v) : "memory");
}
__device__ __forceinline__ void red_release_u(unsigned* p, unsigned v) {
    asm volatile("red.add.release.gpu.u32 [%0], %1;" :: "l"(p), "r"(v) : "memory");
}
__device__ __forceinline__ unsigned ld_acquire_u(const unsigned* p) {
    unsigned v;
    asm volatile("ld.acquire.gpu.u32 %0, [%1];" : "=r"(v) : "l"(p) : "memory");
    return v;
}
// Acquire-poll with bounded backoff (insurance against LTS poll congestion).
__device__ __forceinline__ void poll_cnt(const unsigned* p, unsigned target) {
    int it = 0;
    while (ld_acquire_u(p) < target) {
        if (++it > 64) __nanosleep(64);
    }
}

// ---------------- reset (per replay) ----------------
__global__ void k_reset() {
    int i = threadIdx.x;
    if (i < 8) g_cnt[i].v = 0u;
}

// ---------------- K0: partials for P5 (s<5) and molrow (s==5) ----------------
__global__ void k0_part(const float* __restrict__ mol_vec,
                        const float* __restrict__ solvent_vecs,
                        const float* __restrict__ sp_proj_w,
                        const float* __restrict__ bh_proj_w) {
    int s = blockIdx.y, chunk = blockIdx.x, tid = threadIdx.x;
    const float* vec = (s < 5) ? (solvent_vecs + s * 1024) : mol_vec;
    const float* W   = (s < 5) ? (sp_proj_w + (size_t)s * 1024 * 1024) : bh_proj_w;
    float acc[4] = {0.f, 0.f, 0.f, 0.f};
    int i0 = chunk * 128;
    for (int i = i0; i < i0 + 128; i++) {
        float v = __ldg(&vec[i]);
        const float* Wr = W + (size_t)i * 1024;
#pragma unroll
        for (int u = 0; u < 4; u++) acc[u] += v * Wr[tid + 256 * u];
    }
#pragma unroll
    for (int u = 0; u < 4; u++)
        g_part[(s * 8 + chunk) * 1024 + tid + 256 * u] = acc[u];
}

__global__ void k0b(const float* __restrict__ bh_proj_b) {
    int j = blockIdx.x * 256 + threadIdx.x;
    float a = bh_proj_b[j];
#pragma unroll
    for (int p = 0; p < 8; p++) a += g_part[(40 + p) * 1024 + j];
    g_biasvec[j] = a;
}

__global__ void k1_sp0(const float* __restrict__ ratios,
                       const float* __restrict__ spb) {
    __shared__ float sr[5];
    int t = blockIdx.x, tid = threadIdx.x;
    if (tid < 5) sr[tid] = ratios[t * 5 + tid];
    __syncthreads();
#pragma unroll
    for (int u = 0; u < 4; u++) {
        int j = tid + 256 * u;
        float acc = spb[j];
#pragma unroll
        for (int s = 0; s < 5; s++) {
            float ps = 0.f;
#pragma unroll
            for (int p = 0; p < 8; p++) ps += g_part[(s * 8 + p) * 1024 + j];
            acc += sr[s] * ps;
        }
        g_X[(size_t)t * 1024 + j] = geluf(acc);
    }
}

__global__ void k_demb(const float* __restrict__ desc,
                       const float* __restrict__ dw,
                       const float* __restrict__ db) {
    int t = blockIdx.x, j = threadIdx.x;
    float acc = db[j];
#pragma unroll
    for (int k = 0; k < 6; k++) acc += desc[t * 6 + k] * dw[k * 64 + j];
    g_demb[t * 64 + j] = geluf(acc);
}

// ---------------- generic tiled fp32 GEMM ----------------
__global__ void k_gemm(const float* __restrict__ A, int lda,
                       const float* __restrict__ W, int ldw,
                       const float* __restrict__ bias,
                       const float* __restrict__ res,
                       float* __restrict__ C, int N, int K, int act) {
    __shared__ float As[16][64];
    __shared__ float Ws[16][68];
    int tid = threadIdx.x;
    int bx = blockIdx.x, by = blockIdx.y;
    int tx = tid & 15, ty = tid >> 4;
    float acc[4][4] = {};
    int mBase = by * 64, nBase = bx * 64;
    for (int k0 = 0; k0 < K; k0 += 16) {
        int mA = tid >> 2;
        int kA = (tid & 3) * 4;
        float4 av = *reinterpret_cast<const float4*>(&A[(size_t)(mBase + mA) * lda + k0 + kA]);
        As[kA + 0][mA] = av.x; As[kA + 1][mA] = av.y;
        As[kA + 2][mA] = av.z; As[kA + 3][mA] = av.w;
        int kW = tid >> 4;
        int nW = (tid & 15) * 4;
        float4 wv = *reinterpret_cast<const float4*>(&W[(size_t)(k0 + kW) * ldw + nBase + nW]);
        *reinterpret_cast<float4*>(&Ws[kW][nW]) = wv;
        __syncthreads();
#pragma unroll
        for (int kk = 0; kk < 16; kk++) {
            float4 a = *reinterpret_cast<const float4*>(&As[kk][ty * 4]);
            float4 b = *reinterpret_cast<const float4*>(&Ws[kk][tx * 4]);
            float aa[4] = {a.x, a.y, a.z, a.w};
            float bb[4] = {b.x, b.y, b.z, b.w};
#pragma unroll
            for (int i = 0; i < 4; i++)
#pragma unroll
                for (int j = 0; j < 4; j++) acc[i][j] += aa[i] * bb[j];
        }
        __syncthreads();
    }
#pragma unroll
    for (int i = 0; i < 4; i++) {
        int m = mBase + ty * 4 + i;
#pragma unroll
        for (int j = 0; j < 4; j++) {
            int n = nBase + tx * 4 + j;
            float v = acc[i][j];
            if (bias) v += bias[n];
            if (res)  v += res[(size_t)m * N + n];
            if (act)  v = geluf(v);
            C[(size_t)m * N + n] = v;
        }
    }
}

// ---------------- row LayerNorm (phase A) ----------------
__global__ void k_ln(const float* __restrict__ U, const float* __restrict__ g,
                     const float* __restrict__ b, float* __restrict__ X) {
    __shared__ float red[32];
    int t = blockIdx.x, tid = threadIdx.x;
    float v[4]; float s = 0.f, s2 = 0.f;
#pragma unroll
    for (int u = 0; u < 4; u++) {
        v[u] = U[(size_t)t * 1024 + tid + 256 * u];
        s += v[u]; s2 += v[u] * v[u];
    }
#pragma unroll
    for (int o = 16; o; o >>= 1) {
        s += __shfl_down_sync(~0u, s, o);
        s2 += __shfl_down_sync(~0u, s2, o);
    }
    int lane = tid & 31, w = tid >> 5;
    if (lane == 0) { red[w] = s; red[8 + w] = s2; }
    __syncthreads();
    if (tid == 0) {
        float ts = 0.f, ts2 = 0.f;
#pragma unroll
        for (int q = 0; q < 8; q++) { ts += red[q]; ts2 += red[8 + q]; }
        float m = ts * (1.f / 1024.f);
        float var = ts2 * (1.f / 1024.f) - m * m;
        red[16] = m; red[17] = rsqrtf(var + 1e-5f);
    }
    __syncthreads();
    float m = red[16], rs = red[17];
#pragma unroll
    for (int u = 0; u < 4; u++) {
        int i = tid + 256 * u;
        X[(size_t)t * 1024 + i] = g[i] * (v[u] - m) * rs + b[i];
    }
}

// ---------------- Phase B: persistent sequential kernel ----------------
// SMEM float offsets
constexpr int OFF_W    = 0;        // 6 * 8192 (col-major slices)
constexpr int OFF_LNG  = 49152;    // 2 * 1024 (blocks 0,1 only)
constexpr int OFF_LNB  = 51200;    // 2 * 1024
constexpr int OFF_MG   = 53248;    // 1024 (mu_w * lnG2)
constexpr int OFF_PG   = 54272;    // 1024 (phi_w * lnG2)
constexpr int OFF_R    = 55296;    // 1024 (bh_proj_w row 2112)
constexpr int OFF_X    = 56320;    // 1024 working vector
constexpr int OFF_RED  = 57344;    // 64
constexpr int OFF_B1   = 57408;    // 24
constexpr int OFF_B2   = 57432;    // 24
constexpr int OFF_SCAL = 57456;    // 16
constexpr int SMEMB_FLOATS = 57472;

__global__ void __launch_bounds__(256, 1) k_seq(
    const float* __restrict__ bh_fc1_w, const float* __restrict__ bh_fc1_b,
    const float* __restrict__ bh_fc2_w, const float* __restrict__ bh_fc2_b,
    const float* __restrict__ bh_ln_g,  const float* __restrict__ bh_ln_b,
    const float* __restrict__ bh_proj_w,
    const float* __restrict__ mu_w, const float* __restrict__ mu_b,
    const float* __restrict__ phi_w, const float* __restrict__ phi_b,
    const unsigned char* __restrict__ bmask,
    float* __restrict__ out) {
    extern __shared__ float sm[];
    float* sW    = sm + OFF_W;
    float* sLnG  = sm + OFF_LNG;
    float* sLnB  = sm + OFF_LNB;
    float* sMG   = sm + OFF_MG;
    float* sPG   = sm + OFF_PG;
    float* sR    = sm + OFF_R;
    float* sX    = sm + OFF_X;
    float* sRed  = sm + OFF_RED;
    float* sB1   = sm + OFF_B1;
    float* sB2   = sm + OFF_B2;
    float* sScal = sm + OFF_SCAL;

    int tid = threadIdx.x, lane = tid & 31, w = tid >> 5;
    int g = blockIdx.x;
    int cg = g * COLS;

    // ---- one-time SMEM weight cache: column-major slices ----
    for (int m = 0; m < 6; m++) {
        const float* Wg = (m & 1) ? (bh_fc2_w + (size_t)(m >> 1) * 1048576)
                                  : (bh_fc1_w + (size_t)(m >> 1) * 1048576);
        for (int idx = tid; idx < 8192; idx += 256) {
            int c = idx & 7, row = idx >> 3;
            sW[m * 8192 + c * 1024 + row] = Wg[(size_t)row * 1024 + cg + c];
        }
    }
    for (int idx = tid; idx < 2048; idx += 256) {
        sLnG[idx] = bh_ln_g[idx];
        sLnB[idx] = bh_ln_b[idx];
    }
    for (int idx = tid; idx < 1024; idx += 256) {
        sR[idx]  = bh_proj_w[(size_t)2112 * 1024 + idx];
        sMG[idx] = mu_w[idx]  * bh_ln_g[2048 + idx];
        sPG[idx] = phi_w[idx] * bh_ln_g[2048 + idx];
    }
    if (tid < 24) {
        int i = tid / 8, c = tid % 8;
        sB1[tid] = bh_fc1_b[i * 1024 + cg + c];
        sB2[tid] = bh_fc2_b[i * 1024 + cg + c];
    }
    __syncthreads();

    // ---- precompute head constants: Smg=Σ mu_w*g2, Cmu=Σ mu_w*b2ln + mu_b; same for phi ----
    {
        float smg = 0.f, cmu = 0.f, spg = 0.f, cph = 0.f;
#pragma unroll
        for (int u = 0; u < 4; u++) {
            int i = tid + 256 * u;
            float lb2 = bh_ln_b[2048 + i];
            smg += sMG[i];
            cmu += mu_w[i] * lb2;
            spg += sPG[i];
            cph += phi_w[i] * lb2;
        }
#pragma unroll
        for (int o = 16; o; o >>= 1) {
            smg += __shfl_down_sync(~0u, smg, o);
            cmu += __shfl_down_sync(~0u, cmu, o);
            spg += __shfl_down_sync(~0u, spg, o);
            cph += __shfl_down_sync(~0u, cph, o);
        }
        if (lane == 0) {
            sRed[w] = smg; sRed[8 + w] = cmu; sRed[16 + w] = spg; sRed[24 + w] = cph;
        }
        __syncthreads();
        if (tid == 0) {
            float a = 0, b = 0, c = 0, d = 0;
#pragma unroll
            for (int q = 0; q < 8; q++) {
                a += sRed[q]; b += sRed[8 + q]; c += sRed[16 + q]; d += sRed[24 + q];
            }
            sScal[4] = a;                 // Smg
            sScal[5] = b + mu_b[0];       // Cmu
            sScal[6] = c;                 // Spg
            sScal[7] = d + phi_b[0];      // Cphi
        }
        __syncthreads();
    }
    float Smg = sScal[4], Cmu = sScal[5], Spg = sScal[6], Cph = sScal[7];

    float prev = -1.f;
    unsigned rnd = 0;
    const unsigned* myCnt = &g_cnt[tid < 8 ? tid : 0].v;

    for (int t = 0; t < NT; t++) {
        // ---- z0 = gelu(ybase[t] + prev * r) ----
        {
            float4 y  = *reinterpret_cast<const float4*>(&g_ybase[(size_t)t * 1024 + 4 * tid]);
            float4 r4 = *reinterpret_cast<float4*>(&sR[4 * tid]);
            float4 x0;
            x0.x = geluf(y.x + prev * r4.x);
            x0.y = geluf(y.y + prev * r4.y);
            x0.z = geluf(y.z + prev * r4.z);
            x0.w = geluf(y.w + prev * r4.w);
            *reinterpret_cast<float4*>(&sX[4 * tid]) = x0;
        }
        __syncthreads();

        for (int blk = 0; blk < 3; blk++) {
            // ======== seg A: h[cg+w] = gelu(x @ W1col + b1); warp-per-column ========
            {
                const float4* w1 = reinterpret_cast<const float4*>(&sW[(blk * 2) * 8192 + w * 1024]);
                const float4* x4 = reinterpret_cast<const float4*>(sX);
                float acc = 0.f;
#pragma unroll
                for (int i = 0; i < 8; i++) {
                    float4 xv = x4[i * 32 + lane];
                    float4 wv = w1[i * 32 + lane];
                    acc += xv.x * wv.x + xv.y * wv.y + xv.z * wv.z + xv.w * wv.w;
                }
#pragma unroll
                for (int o = 16; o; o >>= 1) acc += __shfl_xor_sync(~0u, acc, o);
                rnd++;
                if (lane == 0)
                    st_relaxed_f(&g_xchg[rnd & 1][cg + w], geluf(acc + sB1[blk * 8 + w]));
            }
            __syncthreads();
            if (tid == 0) red_release_u(&g_cnt[g & 7].v, 1u);

            // ======== seg B: consume h into sX (keep residual scalar first) ========
            float xres = sX[cg + w];
            if (tid < 8) poll_cnt(myCnt, rnd * 16u);
            __syncthreads();
            {
                float4 hv = __ldcg(reinterpret_cast<const float4*>(&g_xchg[rnd & 1][4 * tid]));
                *reinterpret_cast<float4*>(&sX[4 * tid]) = hv;
            }
            __syncthreads();

            // ======== seg C: u[cg+w] = h @ W2col + b2 + xres ========
            {
                const float4* w2 = reinterpret_cast<const float4*>(&sW[(blk * 2 + 1) * 8192 + w * 1024]);
                const float4* h4 = reinterpret_cast<const float4*>(sX);
                float acc = 0.f;
#pragma unroll
                for (int i = 0; i < 8; i++) {
                    float4 hv = h4[i * 32 + lane];
                    float4 wv = w2[i * 32 + lane];
                    acc += hv.x * wv.x + hv.y * wv.y + hv.z * wv.z + hv.w * wv.w;
                }
#pragma unroll
                for (int o = 16; o; o >>= 1) acc += __shfl_xor_sync(~0u, acc, o);
                rnd++;
                if (lane == 0)
                    st_relaxed_f(&g_xchg[rnd & 1][cg + w], acc + sB2[blk * 8 + w] + xres);
            }
            __syncthreads();
            if (tid == 0) red_release_u(&g_cnt[g & 7].v, 1u);

            // ======== seg D: consume u; LayerNorm (+ fused head on blk 2) ========
            if (tid < 8) poll_cnt(myCnt, rnd * 16u);
            __syncthreads();
            float4 uv = __ldcg(reinterpret_cast<const float4*>(&g_xchg[rnd & 1][4 * tid]));

            if (blk < 2) {
                float s1 = uv.x + uv.y + uv.z + uv.w;
                float s2 = uv.x * uv.x + uv.y * uv.y + uv.z * uv.z + uv.w * uv.w;
#pragma unroll
                for (int o = 16; o; o >>= 1) {
                    s1 += __shfl_down_sync(~0u, s1, o);
                    s2 += __shfl_down_sync(~0u, s2, o);
                }
                if (lane == 0) { sRed[w] = s1; sRed[8 + w] = s2; }
                __syncthreads();
                if (tid == 0) {
                    float ts = 0.f, ts2 = 0.f;
#pragma unroll
                    for (int q = 0; q < 8; q++) { ts += sRed[q]; ts2 += sRed[8 + q]; }
                    float mm = ts * (1.f / 1024.f);
                    float var = ts2 * (1.f / 1024.f) - mm * mm;
                    sScal[0] = mm;
                    sScal[1] = rsqrtf(var + 1e-5f);
                }
                __syncthreads();
                float mm = sScal[0], rs = sScal[1];
                float4 lg = *reinterpret_cast<float4*>(&sLnG[blk * 1024 + 4 * tid]);
                float4 lb = *reinterpret_cast<float4*>(&sLnB[blk * 1024 + 4 * tid]);
                float4 xo;
                xo.x = lg.x * (uv.x - mm) * rs + lb.x;
                xo.y = lg.y * (uv.y - mm) * rs + lb.y;
                xo.z = lg.z * (uv.z - mm) * rs + lb.z;
                xo.w = lg.w * (uv.w - mm) * rs + lb.w;
                *reinterpret_cast<float4*>(&sX[4 * tid]) = xo;
                __syncthreads();
            } else {
                // fused LN + mu/phi head
                float4 mg = *reinterpret_cast<float4*>(&sMG[4 * tid]);
                float4 pg = *reinterpret_cast<float4*>(&sPG[4 * tid]);
                float s1 = uv.x + uv.y + uv.z + uv.w;
                float s2 = uv.x * uv.x + uv.y * uv.y + uv.z * uv.z + uv.w * uv.w;
                float pm = mg.x * uv.x + mg.y * uv.y + mg.z * uv.z + mg.w * uv.w;
                float pp = pg.x * uv.x + pg.y * uv.y + pg.z * uv.z + pg.w * uv.w;
#pragma unroll
                for (int o = 16; o; o >>= 1) {
                    s1 += __shfl_down_sync(~0u, s1, o);
                    s2 += __shfl_down_sync(~0u, s2, o);
                    pm += __shfl_down_sync(~0u, pm, o);
                    pp += __shfl_down_sync(~0u, pp, o);
                }
                if (lane == 0) {
                    sRed[w] = s1; sRed[8 + w] = s2; sRed[16 + w] = pm; sRed[24 + w] = pp;
                }
                __syncthreads();
                if (tid == 0) {
                    float ts = 0.f, ts2 = 0.f, tm = 0.f, tp = 0.f;
#pragma unroll
                    for (int q = 0; q < 8; q++) {
                        ts += sRed[q]; ts2 += sRed[8 + q];
                        tm += sRed[16 + q]; tp += sRed[24 + q];
                    }
                    float mm = ts * (1.f / 1024.f);
                    float var = ts2 * (1.f / 1024.f) - mm * mm;
                    float rs = rsqrtf(var + 1e-5f);
                    float zmu  = rs * (tm - mm * Smg) + Cmu;
                    float zphi = rs * (tp - mm * Spg) + Cph;
                    float mu  = 1.f / (1.f + expf(-zmu));
                    float phi = softplusf(zphi) + 2.f;
                    bool isb = (bmask[t] != 0);
                    float rf = (isb || prev < 0.f) ? mu : prev + mu * (1.f - prev);
                    sScal[2] = rf;
                    if (g == 0) {
                        out[t] = rf;
                        out[NT + t] = mu;
                        out[2 * NT + t] = phi;
                    }
                }
                __syncthreads();
                prev = sScal[2];
            }
        }
    }
}

// ---------------- launch ----------------
extern "C" void kernel_launch(void* const* d_in, const int* in_sizes, int n_in,
                              void* d_out, int out_size) {
    const float* mol_vec      = (const float*)d_in[0];
    const float* solvent_seq  = (const float*)d_in[1];
    const float* desc_seq     = (const float*)d_in[2];
    const float* solvent_vecs = (const float*)d_in[3];
    const unsigned char* bmask = (const unsigned char*)d_in[4];
    const float* sp_proj_w = (const float*)d_in[5];
    const float* sp_proj_b = (const float*)d_in[6];
    const float* sp_fc1_w  = (const float*)d_in[7];
    const float* sp_fc1_b  = (const float*)d_in[8];
    const float* sp_fc2_w  = (const float*)d_in[9];
    const float* sp_fc2_b  = (const float*)d_in[10];
    const float* sp_ln_g   = (const float*)d_in[11];
    const float* sp_ln_b   = (const float*)d_in[12];
    const float* desc_w    = (const float*)d_in[13];
    const float* desc_b    = (const float*)d_in[14];
    const float* bh_proj_w = (const float*)d_in[15];
    const float* bh_proj_b = (const float*)d_in[16];
    const float* bh_fc1_w  = (const float*)d_in[17];
    const float* bh_fc1_b  = (const float*)d_in[18];
    const float* bh_fc2_w  = (const float*)d_in[19];
    const float* bh_fc2_b  = (const float*)d_in[20];
    const float* bh_ln_g   = (const float*)d_in[21];
    const float* bh_ln_b   = (const float*)d_in[22];
    const float* mu_w      = (const float*)d_in[23];
    const float* mu_b      = (const float*)d_in[24];
    const float* phi_w     = (const float*)d_in[25];
    const float* phi_b     = (const float*)d_in[26];
    float* out = (float*)d_out;

    float *pX, *pH, *pU, *pD, *pY, *pBias;
    cudaGetSymbolAddress((void**)&pX, g_X);
    cudaGetSymbolAddress((void**)&pH, g_H);
    cudaGetSymbolAddress((void**)&pU, g_U);
    cudaGetSymbolAddress((void**)&pD, g_demb);
    cudaGetSymbolAddress((void**)&pY, g_ybase);
    cudaGetSymbolAddress((void**)&pBias, g_biasvec);

    k_reset<<<1, 32>>>();
    k0_part<<<dim3(8, 6), 256>>>(mol_vec, solvent_vecs, sp_proj_w, bh_proj_w);
    k0b<<<4, 256>>>(bh_proj_b);
    k1_sp0<<<NT, 256>>>(solvent_seq, sp_proj_b);

    for (int i = 0; i < 3; i++) {
        k_gemm<<<dim3(16, 32), 256>>>(pX, 1024, sp_fc1_w + (size_t)i * 1048576, 1024,
                                      sp_fc1_b + i * 1024, nullptr, pH, 1024, 1024, 1);
        k_gemm<<<dim3(16, 32), 256>>>(pH, 1024, sp_fc2_w + (size_t)i * 1048576, 1024,
                                      sp_fc2_b + i * 1024, pX, pU, 1024, 1024, 0);
        k_ln<<<NT, 256>>>(pU, sp_ln_g + i * 1024, sp_ln_b + i * 1024, pX);
    }

    k_demb<<<NT, 64>>>(desc_seq, desc_w, desc_b);

    k_gemm<<<dim3(16, 32), 256>>>(pX, 1024, bh_proj_w + (size_t)1024 * 1024, 1024,
                                  pBias, nullptr, pH, 1024, 1024, 0);
    k_gemm<<<dim3(16, 32), 256>>>(pD, 64, bh_proj_w + (size_t)2048 * 1024, 1024,
                                  nullptr, pH, pY, 1024, 64, 0);

    cudaFuncSetAttribute(k_seq, cudaFuncAttributeMaxDynamicSharedMemorySize,
                         SMEMB_FLOATS * (int)sizeof(float));
    k_seq<<<GB, 256, SMEMB_FLOATS * sizeof(float)>>>(
        bh_fc1_w, bh_fc1_b, bh_fc2_w, bh_fc2_b, bh_ln_g, bh_ln_b, bh_proj_w,
        mu_w, mu_b, phi_w, phi_b, bmask, out);
}